// round 9
// baseline (speedup 1.0000x reference)
#include <cuda_runtime.h>

#define BB    64
#define TTT   512
#define IN    512
#define HH    1024
#define G4    4096
#define NSTEP 1024
#define KC    32
#define NCTA  128

// 512 MB scratch for G[t][b][4096] = x_t @ Ww^T + (bw + bu)
__device__ float g_G[(size_t)TTT * BB * G4];

// grid-barrier state (zero-initialized; g_cnt returns to 0 every barrier,
// g_gen is compared relatively so monotonic growth across replays is fine)
__device__ unsigned g_cnt;
__device__ volatile unsigned g_gen;

__device__ __forceinline__ unsigned long long fma2(unsigned long long a,
                                                   unsigned long long b,
                                                   unsigned long long c) {
    unsigned long long d;
    asm("fma.rn.f32x2 %0, %1, %2, %3;" : "=l"(d) : "l"(a), "l"(b), "l"(c));
    return d;
}
__device__ __forceinline__ unsigned long long dup2(float v) {
    unsigned int u = __float_as_uint(v);
    return ((unsigned long long)u << 32) | (unsigned long long)u;
}
__device__ __forceinline__ float sigm(float x) { return 1.f / (1.f + __expf(-x)); }

__device__ __forceinline__ void grid_barrier(int tid) {
    __syncthreads();
    if (tid == 0) {
        __threadfence();                       // publish this CTA's h/c stores
        unsigned gen = g_gen;
        if (atomicAdd(&g_cnt, 1u) == NCTA - 1) {
            g_cnt = 0;
            __threadfence();                   // order cnt reset before release
            g_gen = gen + 1;                   // release
        } else {
            while (g_gen == gen) { __nanosleep(64); }
        }
        __threadfence();                       // acquire
    }
    __syncthreads();
}

// ---------------------------------------------------------------------------
// Persistent scan kernel: 128 CTAs (1/SM), loops s = 0..1023.
// Per step: gates = G[t] + h_prev @ Uw^T (CTA tile 64x32, K=1024, KC=32
// double-buffered, thread tile 2Mx4N via fma.rn.f32x2), then fused LSTM
// pointwise update writing h/c straight into d_out. Grid barrier between steps.
// ---------------------------------------------------------------------------
__global__ __launch_bounds__(256) void lstm_scan(const float* __restrict__ Uw,
                                                 float* __restrict__ out) {
    __shared__ __align__(16) unsigned long long sh_h[2 * KC * 66]; // dup'd h, padded
    __shared__ __align__(16) float sh_u[2 * KC * 36];              // Uw slice, padded
    float* gb = sh_u;  // gate-exchange buffer (64 x 34 floats) aliases sh_u

    const int tid  = threadIdx.x;
    const int lane = tid & 31;        // = k within chunk for staging
    const int w    = tid >> 5;        // warp id (8 warps)
    const int g    = blockIdx.x;      // 0..127
    const int j0   = g * 8;
    const int mg   = tid >> 3, ng = tid & 7;
    const int m0   = mg * 2,  n0 = ng * 4;

    for (int s = 0; s < NSTEP; s++) {
        unsigned long long a00 = 0ull, a01 = 0ull, a10 = 0ull, a11 = 0ull;

        if (s > 0) {
            const float* hprev = out + (size_t)(s - 1) * (BB * HH);

            float hr[8], ur[4];
            // prologue: chunk 0 -> regs -> smem buf 0
#pragma unroll
            for (int i = 0; i < 8; i++) hr[i] = hprev[(w + i * 8) * HH + lane];
#pragma unroll
            for (int i = 0; i < 4; i++) {
                int c = w * 4 + i;
                int n = (c >> 3) * HH + j0 + (c & 7);
                ur[i] = Uw[(size_t)n * HH + lane];
            }
#pragma unroll
            for (int i = 0; i < 8; i++) sh_h[lane * 66 + (w + i * 8)] = dup2(hr[i]);
#pragma unroll
            for (int i = 0; i < 4; i++) sh_u[lane * 36 + w * 4 + i] = ur[i];

            int buf = 0;
            const int NCH = HH / KC;  // 32
            for (int ch = 0; ch < NCH; ch++) {
                __syncthreads();  // buf[buf] ready
                if (ch + 1 < NCH) {
                    int kc = (ch + 1) * KC;
#pragma unroll
                    for (int i = 0; i < 8; i++)
                        hr[i] = hprev[(w + i * 8) * HH + kc + lane];
#pragma unroll
                    for (int i = 0; i < 4; i++) {
                        int c = w * 4 + i;
                        int n = (c >> 3) * HH + j0 + (c & 7);
                        ur[i] = Uw[(size_t)n * HH + kc + lane];
                    }
                }
                const unsigned long long* hb = sh_h + buf * (KC * 66) + m0;
                const float* ub = sh_u + buf * (KC * 36) + n0;
#pragma unroll 8
                for (int kk = 0; kk < KC; kk++) {
                    ulonglong2 hp = *(const ulonglong2*)(hb + kk * 66);
                    ulonglong2 up = *(const ulonglong2*)(ub + kk * 36);
                    a00 = fma2(hp.x, up.x, a00);
                    a01 = fma2(hp.x, up.y, a01);
                    a10 = fma2(hp.y, up.x, a10);
                    a11 = fma2(hp.y, up.y, a11);
                }
                if (ch + 1 < NCH) {
                    int nb = buf ^ 1;
#pragma unroll
                    for (int i = 0; i < 8; i++)
                        sh_h[nb * (KC * 66) + lane * 66 + (w + i * 8)] = dup2(hr[i]);
#pragma unroll
                    for (int i = 0; i < 4; i++)
                        sh_u[nb * (KC * 36) + lane * 36 + w * 4 + i] = ur[i];
                }
                buf ^= 1;
            }
        }
        __syncthreads();  // everyone done reading sh_u before gbuf reuse

        // gate exchange: acc -> smem (rows m0,m0+1; cols n0..n0+3)
        *(unsigned long long*)&gb[m0 * 34 + n0]           = a00;
        *(unsigned long long*)&gb[m0 * 34 + n0 + 2]       = a01;
        *(unsigned long long*)&gb[(m0 + 1) * 34 + n0]     = a10;
        *(unsigned long long*)&gb[(m0 + 1) * 34 + n0 + 2] = a11;
        __syncthreads();

        // fused pointwise LSTM update: 512 (b, unit) pairs, 2 per thread
        const int t = s >> 1;
        const size_t gbase = (size_t)(t * BB) * G4;
#pragma unroll
        for (int e = 0; e < 2; e++) {
            int p = tid * 2 + e;
            int b = p >> 3, uu = p & 7;
            size_t gg_idx = gbase + (size_t)b * G4 + j0 + uu;
            float gi = gb[b * 34 + uu]      + g_G[gg_idx];
            float gf = gb[b * 34 + 8 + uu]  + g_G[gg_idx + HH];
            float gG = gb[b * 34 + 16 + uu] + g_G[gg_idx + 2 * HH];
            float go = gb[b * 34 + 24 + uu] + g_G[gg_idx + 3 * HH];

            size_t oidx = (size_t)s * (BB * HH) + (size_t)b * HH + j0 + uu;
            float cp = 0.f;
            if (s > 0) cp = out[(size_t)NSTEP * (BB * HH) + oidx - (BB * HH)];
            float cn = cp * sigm(gf) + sigm(gi) * tanhf(gG);
            float hn = sigm(go) * tanhf(cn);
            out[oidx] = hn;
            out[(size_t)NSTEP * (BB * HH) + oidx] = cn;
        }

        grid_barrier(tid);  // h/c of step s visible chip-wide before step s+1
    }
}

// ---------------------------------------------------------------------------
// Precompute kernel: G[t][b][n] = bias[n] + sum_k x[b][t][k] * Ww[n][k]
// Grid: (128 n-groups of 32, 512 t). Same micro-kernel, K = 512.
// ---------------------------------------------------------------------------
__global__ __launch_bounds__(256) void lstm_pre(const float* __restrict__ x,
                                                const float* __restrict__ Ww,
                                                const float* __restrict__ bw,
                                                const float* __restrict__ bu) {
    __shared__ __align__(16) unsigned long long sh_h[2 * KC * 66];
    __shared__ __align__(16) float sh_u[2 * KC * 36];
    float* gb = sh_u;

    const int tid  = threadIdx.x;
    const int lane = tid & 31;
    const int w    = tid >> 5;
    const int n0g  = blockIdx.x * 32;
    const int t    = blockIdx.y;
    const int mg   = tid >> 3, ng = tid & 7;
    const int m0   = mg * 2,  n0 = ng * 4;

    unsigned long long a00 = 0ull, a01 = 0ull, a10 = 0ull, a11 = 0ull;

    float hr[8], ur[4];
#pragma unroll
    for (int i = 0; i < 8; i++)
        hr[i] = x[((size_t)(w + i * 8) * TTT + t) * IN + lane];
#pragma unroll
    for (int i = 0; i < 4; i++)
        ur[i] = Ww[(size_t)(n0g + w * 4 + i) * IN + lane];
#pragma unroll
    for (int i = 0; i < 8; i++) sh_h[lane * 66 + (w + i * 8)] = dup2(hr[i]);
#pragma unroll
    for (int i = 0; i < 4; i++) sh_u[lane * 36 + w * 4 + i] = ur[i];

    int buf = 0;
    const int NCH = IN / KC;  // 16
    for (int ch = 0; ch < NCH; ch++) {
        __syncthreads();
        if (ch + 1 < NCH) {
            int kc = (ch + 1) * KC;
#pragma unroll
            for (int i = 0; i < 8; i++)
                hr[i] = x[((size_t)(w + i * 8) * TTT + t) * IN + kc + lane];
#pragma unroll
            for (int i = 0; i < 4; i++)
                ur[i] = Ww[(size_t)(n0g + w * 4 + i) * IN + kc + lane];
        }
        const unsigned long long* hb = sh_h + buf * (KC * 66) + m0;
        const float* ub = sh_u + buf * (KC * 36) + n0;
#pragma unroll 8
        for (int kk = 0; kk < KC; kk++) {
            ulonglong2 hp = *(const ulonglong2*)(hb + kk * 66);
            ulonglong2 up = *(const ulonglong2*)(ub + kk * 36);
            a00 = fma2(hp.x, up.x, a00);
            a01 = fma2(hp.x, up.y, a01);
            a10 = fma2(hp.y, up.x, a10);
            a11 = fma2(hp.y, up.y, a11);
        }
        if (ch + 1 < NCH) {
            int nb = buf ^ 1;
#pragma unroll
            for (int i = 0; i < 8; i++)
                sh_h[nb * (KC * 66) + lane * 66 + (w + i * 8)] = dup2(hr[i]);
#pragma unroll
            for (int i = 0; i < 4; i++)
                sh_u[nb * (KC * 36) + lane * 36 + w * 4 + i] = ur[i];
        }
        buf ^= 1;
    }
    __syncthreads();

    *(unsigned long long*)&gb[m0 * 34 + n0]           = a00;
    *(unsigned long long*)&gb[m0 * 34 + n0 + 2]       = a01;
    *(unsigned long long*)&gb[(m0 + 1) * 34 + n0]     = a10;
    *(unsigned long long*)&gb[(m0 + 1) * 34 + n0 + 2] = a11;
    __syncthreads();

    // coalesced flush + bias
#pragma unroll
    for (int i = 0; i < 8; i++) {
        int f = i * 256 + tid;
        int b = f >> 5, c = f & 31;
        int n = n0g + c;
        g_G[((size_t)t * BB + b) * G4 + n] = gb[b * 34 + c] + bw[n] + bu[n];
    }
}

extern "C" void kernel_launch(void* const* d_in, const int* in_sizes, int n_in,
                              void* d_out, int out_size) {
    const float* x  = (const float*)d_in[0];
    const float* Ww = (const float*)d_in[1];
    const float* bw = (const float*)d_in[2];
    const float* Uw = (const float*)d_in[3];
    const float* bu = (const float*)d_in[4];
    float* out = (float*)d_out;

    (void)in_sizes; (void)n_in; (void)out_size;

    lstm_pre<<<dim3(128, 512), 256>>>(x, Ww, bw, bu);
    lstm_scan<<<NCTA, 256>>>(Uw, out);
}